// round 12
// baseline (speedup 1.0000x reference)
#include <cuda_runtime.h>
#include <cuda_fp16.h>
#include <cstdint>

#define HID   512
#define SRC   2048
#define BATCH 64

// CTA tile M=128, N=128, K=512 in 16 KC=32 stages.
// A32: fp32 enc ring (3 slots, 128B/row XOR-swizzled 16B units)
// B  : fp16 W1 ring (4 slots, 80B stride rows)
// A16: fp16 converted enc (2 slots, 80B stride rows)
#define KC        32
#define A32_SLOT  16384
#define B_SLOT    10240
#define A16_SLOT  10240
#define OFF_A32   0                       // 3 slots: 49152
#define OFF_B     49152                   // 4 slots: 40960
#define OFF_A16   90112                   // 2 slots: 20480
#define SMEM_BYTES 110592                 // 108 KB -> 2 CTAs/SM

// ---------------- device scratch ----------------
__device__ __align__(16) __half g_W1h[HID * HID];
__device__ float g_cbias[BATCH * HID];
__device__ float g_part[4][BATCH][SRC];

// ---------------- helpers ----------------
__device__ __forceinline__ unsigned smem_u32(const void* p) {
    return (unsigned)__cvta_generic_to_shared(p);
}
__device__ __forceinline__ void ldsm4(uint32_t r[4], unsigned addr) {
    asm volatile("ldmatrix.sync.aligned.m8n8.x4.shared.b16 {%0,%1,%2,%3}, [%4];"
                 : "=r"(r[0]), "=r"(r[1]), "=r"(r[2]), "=r"(r[3]) : "r"(addr));
}
__device__ __forceinline__ void mma_fp16(float c[4], const uint32_t a[4], const uint32_t b[2]) {
    asm volatile(
        "mma.sync.aligned.m16n8k16.row.col.f32.f16.f16.f32 "
        "{%0,%1,%2,%3}, {%4,%5,%6,%7}, {%8,%9}, {%0,%1,%2,%3};"
        : "+f"(c[0]), "+f"(c[1]), "+f"(c[2]), "+f"(c[3])
        : "r"(a[0]), "r"(a[1]), "r"(a[2]), "r"(a[3]), "r"(b[0]), "r"(b[1]));
}
__device__ __forceinline__ void cp_async16(uint32_t dst, const void* src) {
    asm volatile("cp.async.cg.shared.global [%0], [%1], 16;" :: "r"(dst), "l"(src) : "memory");
}
__device__ __forceinline__ void cp_commit() {
    asm volatile("cp.async.commit_group;" ::: "memory");
}
__device__ __forceinline__ uint32_t packh2(float a, float b) {
    __half2 h = __floats2half2_rn(a, b);
    return *reinterpret_cast<uint32_t*>(&h);
}

// ---------------- kernel 1: W1 -> fp16 ----------------
__global__ void prep_w_kernel(const float* __restrict__ W1w) {
    int i = blockIdx.x * blockDim.x + threadIdx.x;
    if (i < HID * HID) g_W1h[i] = __float2half_rn(W1w[i]);
}

// ---------------- kernel 2: cbias ----------------
__global__ void cbias_kernel(const float* __restrict__ h,
                             const float* __restrict__ W2w,
                             const float* __restrict__ W2b,
                             const float* __restrict__ W1b) {
    __shared__ float hs[HID];
    const int b = blockIdx.x;
    const int o = blockIdx.y * 128 + threadIdx.x;
    for (int k = threadIdx.x; k < HID; k += 128) hs[k] = h[b * HID + k];
    __syncthreads();
    float acc = W2b[o] + W1b[o];
    const float* wr = W2w + o * HID;
#pragma unroll 8
    for (int k = 0; k < HID; k++) acc += hs[k] * wr[k];
    g_cbias[b * HID + o] = acc;
}

// ---------------- kernel 3: overlapped cvt + fp16 GEMM + tanh + V-dot ----------------
// grid (4 nb, 16 st, 64 b); 256 threads = 8 warps (4 M x 2 N).
// Per stage: [wait G(it+1); sync] [issue loads(it+3)] [convert(it+1)] [compute(it)]
__global__ __launch_bounds__(256, 2) void attn_main_kernel(const float* __restrict__ enc,
                                                           const float* __restrict__ Vw) {
    extern __shared__ __align__(128) char smem[];
    const uint32_t sb = smem_u32(smem);

    const int nb  = blockIdx.x;
    const int st  = blockIdx.y;
    const int b   = blockIdx.z;
    const int tid = threadIdx.x;
    const int lane = tid & 31;
    const int wid  = tid >> 5;
    const int warp_m = wid & 3;
    const int warp_n = wid >> 2;
    const int s0 = st * 128;
    const int o0 = nb * 128;

    const float* encRow = enc + (size_t)(b * SRC + s0) * HID;

    float acc[2][8][4];
#pragma unroll
    for (int i = 0; i < 2; i++)
#pragma unroll
        for (int j = 0; j < 8; j++)
#pragma unroll
            for (int r = 0; r < 4; r++) acc[i][j][r] = 0.f;

    // ---- gmem loads for one stage: A fp32 (swizzled) + B fp16 (80B stride) ----
    auto load_gmem = [&](int stage) {
        const int kc = stage * KC;
        const uint32_t a32 = sb + OFF_A32 + (stage % 3) * A32_SLOT;
#pragma unroll
        for (int k = 0; k < 4; ++k) {
            const int q = tid + k * 256;          // 0..1023 16B units
            const int row = q >> 3;
            const int u   = q & 7;
            cp_async16(a32 + row * 128 + ((u ^ (row & 7)) << 4),
                       encRow + (size_t)row * HID + kc + u * 4);
        }
        const uint32_t bb = sb + OFF_B + (stage & 3) * B_SLOT;
#pragma unroll
        for (int k = 0; k < 2; ++k) {
            const int p = tid + k * 256;          // 0..511 16B units
            const int row = p & 127;
            const int u   = p >> 7;               // 0..3
            cp_async16(bb + row * 80 + u * 16,
                       g_W1h + (size_t)(o0 + row) * HID + kc + u * 8);
        }
        cp_commit();
    };

    // ---- convert A fp32 smem -> fp16 smem; conflict-free both directions ----
    auto convert_stage = [&](int stage) {
        const char* a32 = smem + OFF_A32 + (stage % 3) * A32_SLOT;
        char* a16 = smem + OFF_A16 + (stage & 1) * A16_SLOT;
        const int row = tid & 127;
        const int hi  = tid >> 7;                 // 0..1: which 16-col half
#pragma unroll
        for (int m = 0; m < 2; ++m) {
            const int u0 = hi * 4 + 2 * m;        // logical fp32 16B unit
            const float4 f0 = *reinterpret_cast<const float4*>(
                a32 + row * 128 + ((u0 ^ (row & 7)) << 4));
            const float4 f1 = *reinterpret_cast<const float4*>(
                a32 + row * 128 + (((u0 + 1) ^ (row & 7)) << 4));
            uint4 v;
            v.x = packh2(f0.x, f0.y);
            v.y = packh2(f0.z, f0.w);
            v.z = packh2(f1.x, f1.y);
            v.w = packh2(f1.z, f1.w);
            *reinterpret_cast<uint4*>(a16 + row * 80 + (hi * 2 + m) * 16) = v;
        }
    };

    // ---- compute one stage: 2 k16 steps ----
    auto compute_stage = [&](int stage) {
        const uint32_t a16 = sb + OFF_A16 + (stage & 1) * A16_SLOT;
        const uint32_t bb  = sb + OFF_B + (stage & 3) * B_SLOT;
#pragma unroll
        for (int ks = 0; ks < KC; ks += 16) {
            uint32_t a[2][4];
#pragma unroll
            for (int mt = 0; mt < 2; mt++) {
                const int r = warp_m * 32 + mt * 16 + (lane & 15);
                const int u = (ks >> 3) + (lane >> 4);
                ldsm4(a[mt], a16 + r * 80 + u * 16);
            }
#pragma unroll
            for (int ntp = 0; ntp < 4; ntp++) {
                const int br = warp_n * 64 + ntp * 16 + ((lane >> 4) << 3) + (lane & 7);
                const int bu = (ks >> 3) + ((lane >> 3) & 1);
                uint32_t bh[4];
                ldsm4(bh, bb + br * 80 + bu * 16);
#pragma unroll
                for (int mt = 0; mt < 2; mt++) {
#pragma unroll
                    for (int half = 0; half < 2; half++) {
                        mma_fp16(acc[mt][ntp * 2 + half], a[mt], bh + 2 * half);
                    }
                }
            }
        }
    };

    // ---- prologue: 3 stages in flight, convert stage 0 ----
    load_gmem(0);
    load_gmem(1);
    load_gmem(2);
    asm volatile("cp.async.wait_group 2;" ::: "memory");   // G0 complete
    __syncthreads();
    convert_stage(0);

    // ---- mainloop: 16 stages, one sync each ----
#pragma unroll 1
    for (int it = 0; it < 16; ++it) {
        // guarantee G(it+1) complete; never wait on newer groups
        if (it <= 13) asm volatile("cp.async.wait_group 1;" ::: "memory");
        else          asm volatile("cp.async.wait_group 0;" ::: "memory");
        __syncthreads();   // publishes G(it+1), convert(it) STS, frees slots for writers
        if (it < 13) load_gmem(it + 3);   // A32 slot it%3 (readers done), B slot (it+3)&3
        if (it < 15) convert_stage(it + 1);
        compute_stage(it);
    }

    // ---- epilogue: tanh(acc + cbias) * V, reduce over 128 o-columns ----
    float rowsum[2][2];
    rowsum[0][0] = rowsum[0][1] = rowsum[1][0] = rowsum[1][1] = 0.f;

    const float* cbRow = g_cbias + b * HID;
#pragma unroll
    for (int nt = 0; nt < 8; nt++) {
        const int o = o0 + warp_n * 64 + nt * 8 + (lane & 3) * 2;
        const float cb0 = cbRow[o],     v0 = Vw[o];
        const float cb1 = cbRow[o + 1], v1 = Vw[o + 1];
#pragma unroll
        for (int mt = 0; mt < 2; mt++) {
            rowsum[mt][0] += tanhf(acc[mt][nt][0] + cb0) * v0;
            rowsum[mt][0] += tanhf(acc[mt][nt][1] + cb1) * v1;
            rowsum[mt][1] += tanhf(acc[mt][nt][2] + cb0) * v0;
            rowsum[mt][1] += tanhf(acc[mt][nt][3] + cb1) * v1;
        }
    }

    // sRed aliases A32 slot 0; its last reader (convert(15), iter 14) is fenced by
    // the sync at iter 15 which every warp has passed before reaching here.
    float* sRed = reinterpret_cast<float*>(smem);
#pragma unroll
    for (int mt = 0; mt < 2; mt++) {
#pragma unroll
        for (int j = 0; j < 2; j++) {
            float v = rowsum[mt][j];
            v += __shfl_xor_sync(0xffffffffu, v, 1);
            v += __shfl_xor_sync(0xffffffffu, v, 2);
            if ((lane & 3) == 0) {
                const int row = warp_m * 32 + mt * 16 + (lane >> 2) + 8 * j;
                sRed[row * 2 + warp_n] = v;
            }
        }
    }
    __syncthreads();

    if (tid < 128) {
        g_part[nb][b][s0 + tid] = sRed[tid * 2] + sRed[tid * 2 + 1];
    }
}

// ---------------- kernel 4: sum partials + softmax over S ----------------
__global__ void softmax_kernel(float* __restrict__ out) {
    __shared__ float sv[SRC];
    __shared__ float red[256];
    int b = blockIdx.x;
    int tid = threadIdx.x;

    float mx = -1e30f;
    for (int s = tid; s < SRC; s += 256) {
        float v = g_part[0][b][s] + g_part[1][b][s] + g_part[2][b][s] + g_part[3][b][s];
        sv[s] = v;
        mx = fmaxf(mx, v);
    }
    red[tid] = mx;
    __syncthreads();
    for (int st = 128; st > 0; st >>= 1) {
        if (tid < st) red[tid] = fmaxf(red[tid], red[tid + st]);
        __syncthreads();
    }
    mx = red[0];
    __syncthreads();

    float sum = 0.f;
    for (int s = tid; s < SRC; s += 256) {
        float e = expf(sv[s] - mx);
        sv[s] = e;
        sum += e;
    }
    red[tid] = sum;
    __syncthreads();
    for (int st = 128; st > 0; st >>= 1) {
        if (tid < st) red[tid] += red[tid + st];
        __syncthreads();
    }
    float inv = 1.0f / red[0];
    __syncthreads();

    for (int s = tid; s < SRC; s += 256) {
        out[(size_t)b * SRC + s] = sv[s] * inv;
    }
}

// ---------------- launch ----------------
extern "C" void kernel_launch(void* const* d_in, const int* in_sizes, int n_in,
                              void* d_out, int out_size) {
    const float* h    = (const float*)d_in[0];
    const float* enc  = (const float*)d_in[1];
    const float* W1w  = (const float*)d_in[2];
    const float* W1b  = (const float*)d_in[3];
    const float* W2w  = (const float*)d_in[4];
    const float* W2b  = (const float*)d_in[5];
    const float* Vw   = (const float*)d_in[6];
    float* out = (float*)d_out;

    cudaFuncSetAttribute(attn_main_kernel,
                         cudaFuncAttributeMaxDynamicSharedMemorySize, SMEM_BYTES);

    prep_w_kernel<<<(HID * HID + 511) / 512, 512>>>(W1w);
    cbias_kernel<<<dim3(BATCH, 4), 128>>>(h, W2w, W2b, W1b);
    attn_main_kernel<<<dim3(4, SRC / 128, BATCH), 256, SMEM_BYTES>>>(enc, Vw);
    softmax_kernel<<<BATCH, 256>>>(out);
}

// round 13
// speedup vs baseline: 1.1011x; 1.1011x over previous
#include <cuda_runtime.h>
#include <cuda_fp16.h>
#include <cstdint>

#define HID   512
#define SRC   2048
#define BATCH 64

// CTA tile M=128, N=128, K=512 in 8 KC=64 stages. Warp-specialized:
// warps 0-7 consume (MMA), warps 8-15 produce (cp.async + fp32->fp16 convert).
#define KC        64
#define A32_SLOT  32768                  // 128 rows x 64 fp32, 256B/row linear, ring 3
#define A16_SLOT  18432                  // 128 rows x 64 fp16, 144B stride, ring 2
#define B_SLOT    18432                  // 128 rows x 64 fp16, 144B stride, ring 4
#define OFF_A32   0                      // 3 slots:  98304
#define OFF_A16   98304                  // 2 slots:  36864
#define OFF_B     135168                 // 4 slots:  73728
#define SMEM_BYTES 208896                // 204 KB, 1 CTA/SM

// named barrier ids: full = 1+(s&1), empty = 3+(s&1), consumer-only = 5
#define BAR_SYNC(id, cnt)   asm volatile("bar.sync %0, %1;"   :: "r"(id), "r"(cnt) : "memory")
#define BAR_ARRIVE(id, cnt) asm volatile("bar.arrive %0, %1;" :: "r"(id), "r"(cnt) : "memory")

// ---------------- device scratch ----------------
__device__ __align__(16) __half g_W1h[HID * HID];
__device__ float g_cbias[BATCH * HID];
__device__ float g_part[4][BATCH][SRC];

// ---------------- helpers ----------------
__device__ __forceinline__ unsigned smem_u32(const void* p) {
    return (unsigned)__cvta_generic_to_shared(p);
}
__device__ __forceinline__ void ldsm4(uint32_t r[4], unsigned addr) {
    asm volatile("ldmatrix.sync.aligned.m8n8.x4.shared.b16 {%0,%1,%2,%3}, [%4];"
                 : "=r"(r[0]), "=r"(r[1]), "=r"(r[2]), "=r"(r[3]) : "r"(addr));
}
__device__ __forceinline__ void mma_fp16(float c[4], const uint32_t a[4], const uint32_t b[2]) {
    asm volatile(
        "mma.sync.aligned.m16n8k16.row.col.f32.f16.f16.f32 "
        "{%0,%1,%2,%3}, {%4,%5,%6,%7}, {%8,%9}, {%0,%1,%2,%3};"
        : "+f"(c[0]), "+f"(c[1]), "+f"(c[2]), "+f"(c[3])
        : "r"(a[0]), "r"(a[1]), "r"(a[2]), "r"(a[3]), "r"(b[0]), "r"(b[1]));
}
__device__ __forceinline__ void cp_async16(uint32_t dst, const void* src) {
    asm volatile("cp.async.cg.shared.global [%0], [%1], 16;" :: "r"(dst), "l"(src) : "memory");
}
__device__ __forceinline__ void cp_commit() {
    asm volatile("cp.async.commit_group;" ::: "memory");
}
__device__ __forceinline__ uint32_t packh2(float a, float b) {
    __half2 h = __floats2half2_rn(a, b);
    return *reinterpret_cast<uint32_t*>(&h);
}

// ---------------- kernel 1: W1 -> fp16 ----------------
__global__ void prep_w_kernel(const float* __restrict__ W1w) {
    int i = blockIdx.x * blockDim.x + threadIdx.x;
    if (i < HID * HID) g_W1h[i] = __float2half_rn(W1w[i]);
}

// ---------------- kernel 2: cbias ----------------
__global__ void cbias_kernel(const float* __restrict__ h,
                             const float* __restrict__ W2w,
                             const float* __restrict__ W2b,
                             const float* __restrict__ W1b) {
    __shared__ float hs[HID];
    const int b = blockIdx.x;
    const int o = blockIdx.y * 128 + threadIdx.x;
    for (int k = threadIdx.x; k < HID; k += 128) hs[k] = h[b * HID + k];
    __syncthreads();
    float acc = W2b[o] + W1b[o];
    const float* wr = W2w + o * HID;
#pragma unroll 8
    for (int k = 0; k < HID; k++) acc += hs[k] * wr[k];
    g_cbias[b * HID + o] = acc;
}

// ---------------- kernel 3: warp-specialized fused GEMM + tanh + V-dot ----------------
// grid (4 nb, 16 st, 64 b), 512 threads.
__global__ __launch_bounds__(512, 1) void attn_main_kernel(const float* __restrict__ enc,
                                                           const float* __restrict__ Vw) {
    extern __shared__ __align__(128) char smem[];
    const uint32_t sb = smem_u32(smem);

    const int nb  = blockIdx.x;          // fastest -> 4 CTAs share enc rows in L2
    const int st  = blockIdx.y;
    const int b   = blockIdx.z;
    const int tid = threadIdx.x;
    const int lane = tid & 31;
    const int wid  = tid >> 5;
    const int s0 = st * 128;
    const int o0 = nb * 128;

    const float* encRow = enc + (size_t)(b * SRC + s0) * HID;

    if (wid >= 8) {
        // ===================== producers (warps 8-15) =====================
        const int ptid = tid - 256;

        auto load_gmem = [&](int stage) {
            const int kc = stage * KC;
            const uint32_t a32 = sb + OFF_A32 + (stage % 3) * A32_SLOT;
#pragma unroll
            for (int k = 0; k < 8; ++k) {
                const int i = ptid + k * 256;     // 2048 16B units
                const int row = i >> 4;
                const int u   = i & 15;
                cp_async16(a32 + row * 256 + u * 16,
                           encRow + (size_t)row * HID + kc + u * 4);
            }
            const uint32_t bb = sb + OFF_B + (stage & 3) * B_SLOT;
#pragma unroll
            for (int k = 0; k < 4; ++k) {
                const int i = ptid + k * 256;     // 1024 16B units
                const int row = i >> 3;
                const int u   = i & 7;
                cp_async16(bb + row * 144 + u * 16,
                           g_W1h + (size_t)(o0 + row) * HID + kc + u * 8);
            }
            cp_commit();
        };

        // convert own-loaded A32 units -> A16 (144B-stride); self-visibility only
        auto convert_stage = [&](int stage) {
            const uint32_t a32 = sb + OFF_A32 + (stage % 3) * A32_SLOT;
            const uint32_t a16 = sb + OFF_A16 + (stage & 1) * A16_SLOT;
#pragma unroll
            for (int k = 0; k < 8; ++k) {
                const int i = ptid + k * 256;
                const int row = i >> 4;
                const int u   = i & 15;
                float4 f;
                asm volatile("ld.shared.v4.f32 {%0,%1,%2,%3}, [%4];"
                             : "=f"(f.x), "=f"(f.y), "=f"(f.z), "=f"(f.w)
                             : "r"(a32 + row * 256 + u * 16));
                const uint32_t v0 = packh2(f.x, f.y);
                const uint32_t v1 = packh2(f.z, f.w);
                asm volatile("st.shared.v2.u32 [%0], {%1,%2};"
                             :: "r"(a16 + row * 144 + (u >> 1) * 16 + (u & 1) * 8),
                                "r"(v0), "r"(v1) : "memory");
            }
        };

        load_gmem(0);
        load_gmem(1);
#pragma unroll 1
        for (int s = 0; s < 8; ++s) {
            if (s >= 2) BAR_SYNC(3 + (s & 1), 512);       // consumers done stage s-2
            if (s < 6) {
                load_gmem(s + 2);                          // slots freed by the empty wait
                asm volatile("cp.async.wait_group 2;" ::: "memory");  // group s done
            } else if (s == 6) {
                asm volatile("cp.async.wait_group 1;" ::: "memory");
            } else {
                asm volatile("cp.async.wait_group 0;" ::: "memory");
            }
            convert_stage(s);
            BAR_ARRIVE(1 + (s & 1), 512);                  // publish stage s
        }
        // producers exit
    } else {
        // ===================== consumers (warps 0-7) =====================
        const int warp_m = wid & 3;
        const int warp_n = wid >> 2;

        float acc[2][8][4];
#pragma unroll
        for (int i = 0; i < 2; i++)
#pragma unroll
            for (int j = 0; j < 8; j++)
#pragma unroll
                for (int r = 0; r < 4; r++) acc[i][j][r] = 0.f;

#pragma unroll 1
        for (int s = 0; s < 8; ++s) {
            BAR_SYNC(1 + (s & 1), 512);                    // stage s published
            const uint32_t a16 = sb + OFF_A16 + (s & 1) * A16_SLOT;
            const uint32_t bb  = sb + OFF_B + (s & 3) * B_SLOT;
#pragma unroll
            for (int ks = 0; ks < KC; ks += 16) {
                uint32_t a[2][4];
#pragma unroll
                for (int mt = 0; mt < 2; mt++) {
                    const int r = warp_m * 32 + mt * 16 + (lane & 15);
                    const int u = (ks >> 3) + (lane >> 4);
                    ldsm4(a[mt], a16 + r * 144 + u * 16);
                }
#pragma unroll
                for (int ntp = 0; ntp < 4; ntp++) {
                    const int br = warp_n * 64 + ntp * 16 + ((lane >> 4) << 3) + (lane & 7);
                    const int bu = (ks >> 3) + ((lane >> 3) & 1);
                    uint32_t bh[4];
                    ldsm4(bh, bb + br * 144 + bu * 16);
#pragma unroll
                    for (int mt = 0; mt < 2; mt++) {
#pragma unroll
                        for (int half = 0; half < 2; half++) {
                            mma_fp16(acc[mt][ntp * 2 + half], a[mt], bh + 2 * half);
                        }
                    }
                }
            }
            BAR_ARRIVE(3 + (s & 1), 512);                  // release stage s buffers
        }

        // ---- epilogue: tanh(acc + cbias) * V, reduce over 128 o-columns ----
        float rowsum[2][2];
        rowsum[0][0] = rowsum[0][1] = rowsum[1][0] = rowsum[1][1] = 0.f;

        const float* cbRow = g_cbias + b * HID;
#pragma unroll
        for (int nt = 0; nt < 8; nt++) {
            const int o = o0 + warp_n * 64 + nt * 8 + (lane & 3) * 2;
            const float cb0 = cbRow[o],     v0 = Vw[o];
            const float cb1 = cbRow[o + 1], v1 = Vw[o + 1];
#pragma unroll
            for (int mt = 0; mt < 2; mt++) {
                rowsum[mt][0] += tanhf(acc[mt][nt][0] + cb0) * v0;
                rowsum[mt][0] += tanhf(acc[mt][nt][1] + cb1) * v1;
                rowsum[mt][1] += tanhf(acc[mt][nt][2] + cb0) * v0;
                rowsum[mt][1] += tanhf(acc[mt][nt][3] + cb1) * v1;
            }
        }

        // sRed aliases A32 slot 0: producers' last access to it (convert(6)) is
        // ordered before their full[0] arrive at s=6, which consumers synced.
        float* sRed = reinterpret_cast<float*>(smem);
#pragma unroll
        for (int mt = 0; mt < 2; mt++) {
#pragma unroll
            for (int j = 0; j < 2; j++) {
                float v = rowsum[mt][j];
                v += __shfl_xor_sync(0xffffffffu, v, 1);
                v += __shfl_xor_sync(0xffffffffu, v, 2);
                if ((lane & 3) == 0) {
                    const int row = warp_m * 32 + mt * 16 + (lane >> 2) + 8 * j;
                    sRed[row * 2 + warp_n] = v;
                }
            }
        }
        BAR_SYNC(5, 256);                                  // consumers only

        if (tid < 128) {
            g_part[nb][b][s0 + tid] = sRed[tid * 2] + sRed[tid * 2 + 1];
        }
    }
}

// ---------------- kernel 4: sum partials + softmax over S ----------------
__global__ void softmax_kernel(float* __restrict__ out) {
    __shared__ float sv[SRC];
    __shared__ float red[256];
    int b = blockIdx.x;
    int tid = threadIdx.x;

    float mx = -1e30f;
    for (int s = tid; s < SRC; s += 256) {
        float v = g_part[0][b][s] + g_part[1][b][s] + g_part[2][b][s] + g_part[3][b][s];
        sv[s] = v;
        mx = fmaxf(mx, v);
    }
    red[tid] = mx;
    __syncthreads();
    for (int st = 128; st > 0; st >>= 1) {
        if (tid < st) red[tid] = fmaxf(red[tid], red[tid + st]);
        __syncthreads();
    }
    mx = red[0];
    __syncthreads();

    float sum = 0.f;
    for (int s = tid; s < SRC; s += 256) {
        float e = expf(sv[s] - mx);
        sv[s] = e;
        sum += e;
    }
    red[tid] = sum;
    __syncthreads();
    for (int st = 128; st > 0; st >>= 1) {
        if (tid < st) red[tid] += red[tid + st];
        __syncthreads();
    }
    float inv = 1.0f / red[0];
    __syncthreads();

    for (int s = tid; s < SRC; s += 256) {
        out[(size_t)b * SRC + s] = sv[s] * inv;
    }
}

// ---------------- launch ----------------
extern "C" void kernel_launch(void* const* d_in, const int* in_sizes, int n_in,
                              void* d_out, int out_size) {
    const float* h    = (const float*)d_in[0];
    const float* enc  = (const float*)d_in[1];
    const float* W1w  = (const float*)d_in[2];
    const float* W1b  = (const float*)d_in[3];
    const float* W2w  = (const float*)d_in[4];
    const float* W2b  = (const float*)d_in[5];
    const float* Vw   = (const float*)d_in[6];
    float* out = (float*)d_out;

    cudaFuncSetAttribute(attn_main_kernel,
                         cudaFuncAttributeMaxDynamicSharedMemorySize, SMEM_BYTES);

    prep_w_kernel<<<(HID * HID + 511) / 512, 512>>>(W1w);
    cbias_kernel<<<dim3(BATCH, 4), 128>>>(h, W2w, W2b, W1b);
    attn_main_kernel<<<dim3(4, SRC / 128, BATCH), 512, SMEM_BYTES>>>(enc, Vw);
    softmax_kernel<<<BATCH, 256>>>(out);
}